// round 3
// baseline (speedup 1.0000x reference)
#include <cuda_runtime.h>
#include <math.h>

// ---- problem constants ----
#define HH    256
#define WW    256
#define WH    129          // rfft last-dim
#define DIM   128
#define HID   512
#define BB    4
#define NLAY  4
#define NPIX  65536        // HH*WW

// ---- static scratch (allocation-free) ----
__device__ float  g_h   [BB*DIM*NPIX];     // 128 MB residual stream
__device__ float  g_t512[BB*HID*NPIX];     // 512 MB mlp hidden
__device__ float  g_t128[BB*DIM*NPIX];     // 128 MB mlp out / spectral out
__device__ float2 g_f   [(size_t)BB*DIM*HH*WH]; // 135 MB spectrum

__device__ __forceinline__ float2 cmul(float2 a, float2 b) {
    return make_float2(a.x*b.x - a.y*b.y, a.x*b.y + a.y*b.x);
}

// ============================================================
// encoder: h = (enc_w @ x + enc_b)*8 + pos_emb
// ============================================================
__global__ void __launch_bounds__(256) encode_kernel(
    const float* __restrict__ x, const float* __restrict__ ew,
    const float* __restrict__ eb, const float* __restrict__ pos)
{
    int idx = blockIdx.x * 256 + threadIdx.x;      // < 2^25
    int p = idx & (NPIX - 1);
    int c = (idx >> 16) & (DIM - 1);
    int b = idx >> 23;
    float x0 = x[(b*2 + 0)*NPIX + p];
    float x1 = x[(b*2 + 1)*NPIX + p];
    float v = (ew[c*2 + 0]*x0 + ew[c*2 + 1]*x1 + eb[c]) * 8.0f + pos[c*NPIX + p];
    g_h[idx] = v;
}

// ============================================================
// generic 1x1-conv GEMM: Y[o,p] = sum_c W[o,c] X[c,p] + bias[o]
// optional SiLU, optional residual add (R). 64x64 tile, 4x4/thread.
// ============================================================
template<int ACT, int RES>
__global__ void __launch_bounds__(256) conv_gemm(
    const float* __restrict__ Wm, const float* __restrict__ bias,
    const float* __restrict__ X,  float* __restrict__ Y,
    const float* __restrict__ R,  int C, int O)
{
    __shared__ float Ws[16][64];
    __shared__ float Xs[16][64];
    int b = blockIdx.z;
    const float* Xb = X + (long long)b * C * NPIX;
    float*       Yb = Y + (long long)b * O * NPIX;
    const float* Rb = R + (long long)b * O * NPIX;

    int p0 = blockIdx.x * 64;
    int o0 = blockIdx.y * 64;
    int tid = threadIdx.x;
    int tx = tid & 15, ty = tid >> 4;

    float acc[4][4] = {};

    for (int k0 = 0; k0 < C; k0 += 16) {
        { // W tile 64x16 -> transposed to Ws[k][o]
            int row = tid >> 2;
            int c4  = (tid & 3) * 4;
            float4 w4 = *(const float4*)&Wm[(o0 + row) * C + k0 + c4];
            Ws[c4+0][row] = w4.x; Ws[c4+1][row] = w4.y;
            Ws[c4+2][row] = w4.z; Ws[c4+3][row] = w4.w;
        }
        { // X tile 16x64
            int row = tid >> 4;
            int c4  = (tid & 15) * 4;
            *(float4*)&Xs[row][c4] =
                *(const float4*)&Xb[(long long)(k0 + row) * NPIX + p0 + c4];
        }
        __syncthreads();
#pragma unroll
        for (int k = 0; k < 16; k++) {
            float4 a4 = *(const float4*)&Ws[k][ty*4];
            float4 b4 = *(const float4*)&Xs[k][tx*4];
            float av[4] = {a4.x, a4.y, a4.z, a4.w};
            float bv[4] = {b4.x, b4.y, b4.z, b4.w};
#pragma unroll
            for (int i = 0; i < 4; i++)
#pragma unroll
                for (int j = 0; j < 4; j++)
                    acc[i][j] += av[i] * bv[j];
        }
        __syncthreads();
    }

#pragma unroll
    for (int i = 0; i < 4; i++) {
        int o = o0 + ty*4 + i;
        float bi = bias[o];
        long long off = (long long)o * NPIX + p0 + tx*4;
        float v[4];
#pragma unroll
        for (int j = 0; j < 4; j++) {
            float y = acc[i][j] + bi;
            if (ACT) y = y / (1.0f + __expf(-y));   // SiLU
            v[j] = y;
        }
        if (RES) {
            float4 r4 = *(const float4*)&Rb[off];
            v[0] += r4.x; v[1] += r4.y; v[2] += r4.z; v[3] += r4.w;
        }
        float4 y4 = make_float4(v[0], v[1], v[2], v[3]);
        *(float4*)&Yb[off] = y4;
    }
}

// ============================================================
// FFT helpers: one warp per 256-point transform, smem workspace.
// tw[k] = exp(-2*pi*i*k/256), k=0..127
// ============================================================

// rows forward: real 256 -> complex 129 (natural order, unnormalized fwd DFT)
__global__ void __launch_bounds__(256) fft_row_fwd(
    const float* __restrict__ in, float2* __restrict__ out)
{
    __shared__ float2 tw[128];
    __shared__ float2 work[8][256];
    int tid = threadIdx.x;
    if (tid < 128) {
        float s, c; sincosf(-3.14159265358979f * tid / 128.0f, &s, &c);
        tw[tid] = make_float2(c, s);
    }
    __syncthreads();
    int warp = tid >> 5, lane = tid & 31;
    int row = blockIdx.x * 8 + warp;
    float2* a = work[warp];
    const float* src = in + (long long)row * 256;
#pragma unroll
    for (int j = 0; j < 8; j++) { int i = lane + 32*j; a[i] = make_float2(src[i], 0.f); }
    __syncwarp();
#pragma unroll
    for (int j = 0; j < 8; j++) {
        int i = lane + 32*j; int r = __brev(i) >> 24;
        if (i < r) { float2 t = a[i]; a[i] = a[r]; a[r] = t; }
    }
    __syncwarp();
    for (int half = 1; half < 256; half <<= 1) {
        int step = 128 / half;
#pragma unroll
        for (int j = 0; j < 4; j++) {
            int idx = lane + 32*j;
            int pos = idx & (half - 1);
            int i0  = 2*idx - pos;
            float2 w = tw[pos * step];
            float2 t = cmul(w, a[i0 + half]);
            float2 u = a[i0];
            a[i0 + half] = make_float2(u.x - t.x, u.y - t.y);
            a[i0]        = make_float2(u.x + t.x, u.y + t.y);
        }
        __syncwarp();
    }
    float2* dst = out + (long long)row * WH;
#pragma unroll
    for (int j = 0; j < 5; j++) { int i = lane + 32*j; if (i < WH) dst[i] = a[i]; }
}

// columns: fwd DIF (natural->bitrev), filter at brev(ky) incl. mask and 1/65536,
// inverse DIT (bitrev->natural). In place on g_f.
__global__ void __launch_bounds__(256) fft_col_filter(
    float2* __restrict__ f, const float* __restrict__ mags,
    const float* __restrict__ phases)
{
    __shared__ float2 tw[128];
    __shared__ float2 work[8][256];
    int tid = threadIdx.x;
    if (tid < 128) {
        float s, c; sincosf(-3.14159265358979f * tid / 128.0f, &s, &c);
        tw[tid] = make_float2(c, s);
    }
    __syncthreads();
    int warp = tid >> 5, lane = tid & 31;
    int col = blockIdx.x * 8 + warp;                // < BB*DIM*WH = 66048 exactly
    int b  = col / (DIM * WH);
    int c  = (col / WH) % DIM;
    int kx = col % WH;
    float2* base = f + ((long long)(b * DIM + c)) * HH * WH + kx;
    float2* a = work[warp];
#pragma unroll
    for (int j = 0; j < 8; j++) { int i = lane + 32*j; a[i] = base[(long long)i * WH]; }
    __syncwarp();
    // forward DIF
    for (int half = 128; half >= 1; half >>= 1) {
        int step = 128 / half;
#pragma unroll
        for (int j = 0; j < 4; j++) {
            int idx = lane + 32*j;
            int pos = idx & (half - 1);
            int i0  = 2*idx - pos;
            float2 u = a[i0];
            float2 v = a[i0 + half];
            a[i0] = make_float2(u.x + v.x, u.y + v.y);
            a[i0 + half] = cmul(tw[pos * step], make_float2(u.x - v.x, u.y - v.y));
        }
        __syncwarp();
    }
    // filter: position r holds spectrum bin ky = brev(r)
    const float invn = 1.0f / 65536.0f;
#pragma unroll
    for (int j = 0; j < 8; j++) {
        int r  = lane + 32*j;
        int ky = __brev(r) >> 24;
        int ry = (ky < 128) ? ky : ky - 256;
        if (kx*kx + ry*ry <= 16384) {
            long long si = ((long long)c * 256 + ky) * WH + kx;
            float m  = mags[si];
            float ph = phases[si];
            float sg = 1.0f / (1.0f + __expf(-m));
            float s, co; sincosf(ph, &s, &co);
            float2 fl = make_float2(sg * co * invn, sg * s * invn);
            a[r] = cmul(a[r], fl);
        } else {
            a[r] = make_float2(0.f, 0.f);
        }
    }
    __syncwarp();
    // inverse DIT (conjugate twiddles, unnormalized)
    for (int half = 1; half < 256; half <<= 1) {
        int step = 128 / half;
#pragma unroll
        for (int j = 0; j < 4; j++) {
            int idx = lane + 32*j;
            int pos = idx & (half - 1);
            int i0  = 2*idx - pos;
            float2 w = tw[pos * step]; w.y = -w.y;
            float2 t = cmul(w, a[i0 + half]);
            float2 u = a[i0];
            a[i0 + half] = make_float2(u.x - t.x, u.y - t.y);
            a[i0]        = make_float2(u.x + t.x, u.y + t.y);
        }
        __syncwarp();
    }
#pragma unroll
    for (int j = 0; j < 8; j++) { int i = lane + 32*j; base[(long long)i * WH] = a[i]; }
}

// rows inverse: complex 129 (Hermitian-extended) -> real 256
__global__ void __launch_bounds__(256) fft_row_inv(
    const float2* __restrict__ in, float* __restrict__ out)
{
    __shared__ float2 tw[128];
    __shared__ float2 work[8][256];
    int tid = threadIdx.x;
    if (tid < 128) {
        float s, c; sincosf(-3.14159265358979f * tid / 128.0f, &s, &c);
        tw[tid] = make_float2(c, s);
    }
    __syncthreads();
    int warp = tid >> 5, lane = tid & 31;
    int row = blockIdx.x * 8 + warp;
    const float2* src = in + (long long)row * WH;
    float2* a = work[warp];
#pragma unroll
    for (int j = 0; j < 8; j++) {
        int i = lane + 32*j;
        float2 v;
        if (i < WH) v = src[i];
        else { v = src[256 - i]; v.y = -v.y; }
        a[i] = v;
    }
    __syncwarp();
#pragma unroll
    for (int j = 0; j < 8; j++) {
        int i = lane + 32*j; int r = __brev(i) >> 24;
        if (i < r) { float2 t = a[i]; a[i] = a[r]; a[r] = t; }
    }
    __syncwarp();
    for (int half = 1; half < 256; half <<= 1) {
        int step = 128 / half;
#pragma unroll
        for (int j = 0; j < 4; j++) {
            int idx = lane + 32*j;
            int pos = idx & (half - 1);
            int i0  = 2*idx - pos;
            float2 w = tw[pos * step]; w.y = -w.y;
            float2 t = cmul(w, a[i0 + half]);
            float2 u = a[i0];
            a[i0 + half] = make_float2(u.x - t.x, u.y - t.y);
            a[i0]        = make_float2(u.x + t.x, u.y + t.y);
        }
        __syncwarp();
    }
    float* dst = out + (long long)row * 256;
#pragma unroll
    for (int j = 0; j < 8; j++) { int i = lane + 32*j; dst[i] = a[i].x; }
}

// ============================================================
// decoder: out = (dec_w @ h + dec_b) / 8
// ============================================================
__global__ void __launch_bounds__(256) decode_kernel(
    const float* __restrict__ dw, const float* __restrict__ db,
    float* __restrict__ out)
{
    int idx = blockIdx.x * 256 + threadIdx.x;   // < BB*NPIX
    int p = idx & (NPIX - 1);
    int b = idx >> 16;
    const float* h = g_h + (long long)b * DIM * NPIX + p;
    float a0 = 0.f, a1 = 0.f;
#pragma unroll 8
    for (int c = 0; c < DIM; c++) {
        float v = h[(long long)c * NPIX];
        a0 += dw[c] * v;
        a1 += dw[DIM + c] * v;
    }
    out[(b*2 + 0)*NPIX + p] = (a0 + db[0]) * 0.125f;
    out[(b*2 + 1)*NPIX + p] = (a1 + db[1]) * 0.125f;
}

// ============================================================
// launcher
// ============================================================
extern "C" void kernel_launch(void* const* d_in, const int* in_sizes, int n_in,
                              void* d_out, int out_size)
{
    const float* x      = (const float*)d_in[0];
    const float* enc_w  = (const float*)d_in[1];
    const float* enc_b  = (const float*)d_in[2];
    const float* pos    = (const float*)d_in[3];
    const float* w1     = (const float*)d_in[4];
    const float* b1     = (const float*)d_in[5];
    const float* w2     = (const float*)d_in[6];
    const float* b2     = (const float*)d_in[7];
    const float* mags   = (const float*)d_in[8];
    const float* phases = (const float*)d_in[9];
    const float* ow     = (const float*)d_in[10];
    const float* ob     = (const float*)d_in[11];
    const float* dw     = (const float*)d_in[12];
    const float* db     = (const float*)d_in[13];
    float* out = (float*)d_out;

    float *ph_, *pt512, *pt128; float2* pf;
    cudaGetSymbolAddress((void**)&ph_,   g_h);
    cudaGetSymbolAddress((void**)&pt512, g_t512);
    cudaGetSymbolAddress((void**)&pt128, g_t128);
    cudaGetSymbolAddress((void**)&pf,    g_f);

    encode_kernel<<<(BB*DIM*NPIX)/256, 256>>>(x, enc_w, enc_b, pos);

    const int nrowblk = (BB*DIM*HH) / 8;       // 16384
    const int ncolblk = (BB*DIM*WH) / 8;       // 8256

    for (int i = 0; i < NLAY; i++) {
        // mlp1: hidden = silu(W1 h + b1)
        conv_gemm<1,0><<<dim3(NPIX/64, HID/64, BB), 256>>>(
            w1 + (long long)i*HID*DIM, b1 + i*HID, ph_, pt512, nullptr, DIM, HID);
        // mlp2: x1 = W2 hidden + b2
        conv_gemm<0,0><<<dim3(NPIX/64, DIM/64, BB), 256>>>(
            w2 + (long long)i*DIM*HID, b2 + i*DIM, pt512, pt128, nullptr, HID, DIM);
        // spectral conv
        fft_row_fwd<<<nrowblk, 256>>>(pt128, pf);
        fft_col_filter<<<ncolblk, 256>>>(pf,
            mags   + (long long)i*DIM*HH*WH,
            phases + (long long)i*DIM*HH*WH);
        fft_row_inv<<<nrowblk, 256>>>(pf, pt128);
        // oxo + residual: h = W3 x1 + b3 + h
        conv_gemm<0,1><<<dim3(NPIX/64, DIM/64, BB), 256>>>(
            ow + (long long)i*DIM*DIM, ob + i*DIM, pt128, ph_, ph_, DIM, DIM);
    }

    decode_kernel<<<(BB*NPIX)/256, 256>>>(dw, db, out);
}